// round 10
// baseline (speedup 1.0000x reference)
#include <cuda_runtime.h>

#define NVW   9
#define HSZ   480
#define WSZ   640
#define NPIX  (HSZ*WSZ)
#define GD    96
#define NCELL (GD*GD*GD)
#define PIXB4 (NPIX/(256*4))   // 300 blocks per view image, 4 px/thread
#define PIXB  (NPIX/256)       // 1200 blocks per view image, 1 px/thread
#define GRIDB (NCELL/256)      // 3456 blocks for voxel grid
#define TMMB  (NVW*PIXB4)      // 2700 target-minmax blocks
#define DFZB  (NVW*NPIX/(4*256)) // 2700 dflat-zero blocks (uint4)
#define NSZB  (NVW*NPIX/256)   // 10800 ns4-zero blocks (float4)

// ==== zero-canonical scratch. Cleaning placement per buffer:            ====
// g_last  : cleaned by L2 grid part (after read)                          ====
// g_dflat : zeroed by L1 (before L2 project writes it)                    ====
// g_ns4   : zeroed by L2 (before L3 splat writes it)                      ====
// scalars : cleaned by k_loss                                             ====
__device__ __align__(16) int          g_last[NCELL];        // idx+1, 0 = empty
__device__ float                      g_grid[NCELL];        // fully rewritten each call
__device__ __align__(16) unsigned int g_dflat[NVW*NPIX];    // ~bits(z), atomicMax == min-z, 0 = no hit
__device__ __align__(16) float4       g_ns4[NVW*NPIX];      // xyz=nsum, w=ncnt
__device__ unsigned int g_dminE[NVW], g_tminE[NVW];          // ~bits of min, atomicMax, 0-canonical
__device__ unsigned int g_dmax[NVW],  g_tmax[NVW];           // bits of max (vals>=0), 0-canonical
__device__ float        g_lsum[NVW];
__device__ int          g_vcnt[NVW];

// XLA:CPU dot (no FMA contraction, left-assoc, strict rn): ((p0*m0 + p1*m1) + p2*m2)
__device__ __forceinline__ float dotrow(const float* M, float px, float py, float pz) {
    return __fadd_rn(__fadd_rn(__fmul_rn(px, M[0]), __fmul_rn(py, M[1])),
                     __fmul_rn(pz, M[2]));
}
// u = rn( (f*x)/zs + c ), strict
__device__ __forceinline__ int proj_pix(float f, float c, float x, float zs) {
    return __float2int_rn(__fadd_rn(__fdiv_rn(__fmul_rn(f, x), zs), c));
}

__device__ __forceinline__ void load_view_consts(const float* __restrict__ vm,
                                                 const float* __restrict__ intr,
                                                 float* s_vm, float* s_in) {
    int t = threadIdx.x;
    if (t < NVW * 12) s_vm[t] = vm[(t / 12) * 16 + (t % 12)];   // rows 0..2 of 4x4
    if (t < NVW * 4) {
        int v = t >> 2, k = t & 3;
        int off = (k == 0) ? 0 : (k == 1) ? 5 : (k == 2) ? 2 : 6; // fx,fy,cx,cy
        s_in[t] = intr[v * 16 + off];
    }
    __syncthreads();
}

// -- L1 fused: [0,projB) scatter ; [+TMMB) target minmax ; [+DFZB) zero dflat
__global__ void k_scatter_tmm(const int4* __restrict__ coords,
                              const float* __restrict__ tgt, int n, int projB) {
    int b = blockIdx.x;
    if (b < projB) {
        int i = b * blockDim.x + threadIdx.x;
        if (i >= n) return;
        int4 q = coords[i];                    // (.x=0, .y=c1, .z=c2, .w=c3)
        atomicMax(&g_last[(q.w * GD + q.z) * GD + q.y], i + 1);  // last-write-wins
        return;
    }
    if (b >= projB + TMMB) {                   // zero g_dflat (uint4)
        int i = (b - projB - TMMB) * blockDim.x + threadIdx.x;
        reinterpret_cast<uint4*>(g_dflat)[i] = make_uint4(0u, 0u, 0u, 0u);
        return;
    }
    int bb = b - projB;
    int v = bb / PIXB4;
    int p4 = (bb % PIXB4) * blockDim.x + threadIdx.x;
    float4 dt = reinterpret_cast<const float4*>(tgt)[v * (NPIX/4) + p4];
    float mnt = fminf(fminf(dt.x, dt.y), fminf(dt.z, dt.w));
    float mxt = fmaxf(fmaxf(dt.x, dt.y), fmaxf(dt.z, dt.w));
    int cnt = (dt.x != 0.f) + (dt.y != 0.f) + (dt.z != 0.f) + (dt.w != 0.f);
    for (int o = 16; o; o >>= 1) {
        mnt = fminf(mnt, __shfl_down_sync(0xffffffffu, mnt, o));
        mxt = fmaxf(mxt, __shfl_down_sync(0xffffffffu, mxt, o));
        cnt += __shfl_down_sync(0xffffffffu, cnt, o);
    }
    __shared__ float smnt[8], smxt[8];
    __shared__ int sc[8];
    int wid = threadIdx.x >> 5, lid = threadIdx.x & 31;
    if (lid == 0) { smnt[wid] = mnt; smxt[wid] = mxt; sc[wid] = cnt; }
    __syncthreads();
    if (threadIdx.x == 0) {
        for (int w = 1; w < 8; w++) {
            mnt = fminf(mnt, smnt[w]); mxt = fmaxf(mxt, smxt[w]); cnt += sc[w];
        }
        atomicMax(&g_tminE[v], ~__float_as_uint(mnt));   // encoded min (0-canonical)
        atomicMax(&g_tmax[v],   __float_as_uint(mxt));
        atomicAdd(&g_vcnt[v], cnt);
    }
}

// -- L2 fused: [0,projB) project ; [+GRIDB) grid+reset ; [+NSZB) zero ns4 ---
__global__ void k_grid_project(const int4* __restrict__ coords,
                               const float* __restrict__ origin,
                               const float* __restrict__ vm,
                               const float* __restrict__ intr,
                               const float* __restrict__ sdf, int n, int projB) {
    int b = blockIdx.x;
    if (b >= projB) {
        if (b < projB + GRIDB) {               // materialize voxel grid + clean g_last
            int c = (b - projB) * blockDim.x + threadIdx.x;
            int idx = g_last[c];
            g_grid[c] = (idx > 0) ? __ldg(&sdf[idx - 1]) : 0.f;
            if (idx > 0) g_last[c] = 0;        // self-clean (skip if clean)
        } else {                               // zero g_ns4 (float4)
            int i = (b - projB - GRIDB) * blockDim.x + threadIdx.x;
            g_ns4[i] = make_float4(0.f, 0.f, 0.f, 0.f);
        }
        return;
    }
    __shared__ float s_vm[NVW * 12];
    __shared__ float s_in[NVW * 4];
    load_view_consts(vm, intr, s_vm, s_in);
    int i = b * blockDim.x + threadIdx.x;
    if (i >= n) return;
    int4 q = coords[i];
    float px = __fadd_rn((float)q.w, __ldg(&origin[0]));
    float py = __fadd_rn((float)q.z, __ldg(&origin[1]));
    float pz = __fadd_rn((float)q.y, __ldg(&origin[2]));
    #pragma unroll
    for (int v = 0; v < NVW; v++) {
        const float* M = &s_vm[v * 12];
        float x = __fadd_rn(dotrow(M,     px, py, pz), M[3]);
        float y = __fadd_rn(dotrow(M + 4, px, py, pz), M[7]);
        float z = __fadd_rn(dotrow(M + 8, px, py, pz), M[11]);
        float zs = (fabsf(z) < 1e-6f) ? 1e-6f : z;
        int u = proj_pix(s_in[v*4+0], s_in[v*4+2], x, zs);
        int w = proj_pix(s_in[v*4+1], s_in[v*4+3], y, zs);
        if (z > 0.025f && z < 100.0f && u >= 0 && u < WSZ && w >= 0 && w < HSZ)
            atomicMax(&g_dflat[v * NPIX + w * WSZ + u], ~__float_as_uint(z));
    }
}

// ------ L3 fused: [0,projB) splat ; [projB,..) depth-image minmax ----------
__global__ void k_splat_dmm(const int4* __restrict__ coords,
                            const float* __restrict__ origin,
                            const float* __restrict__ vm,
                            const float* __restrict__ intr, int n, int projB) {
    if ((int)blockIdx.x < projB) {
        __shared__ float s_vm[NVW * 12];
        __shared__ float s_in[NVW * 4];
        load_view_consts(vm, intr, s_vm, s_in);
        int i = blockIdx.x * blockDim.x + threadIdx.x;
        if (i >= n) return;
        int4 q = coords[i];
        float px = __fadd_rn((float)q.w, __ldg(&origin[0]));
        float py = __fadd_rn((float)q.z, __ldg(&origin[1]));
        float pz = __fadd_rn((float)q.y, __ldg(&origin[2]));
        float na = 0.f, nb = 0.f, nc = 0.f;
        if (q.w >= 1 && q.w <= GD-2 && q.z >= 1 && q.z <= GD-2 && q.y >= 1 && q.y <= GD-2) {
            int base = (q.w * GD + q.z) * GD + q.y;
            na = __fsub_rn(g_grid[base + 1],     g_grid[base - 1]);
            nb = __fsub_rn(g_grid[base + GD],    g_grid[base - GD]);
            nc = __fsub_rn(g_grid[base + GD*GD], g_grid[base - GD*GD]);
        }
        #pragma unroll
        for (int v = 0; v < NVW; v++) {
            const float* M = &s_vm[v * 12];
            float x = __fadd_rn(dotrow(M,     px, py, pz), M[3]);
            float y = __fadd_rn(dotrow(M + 4, px, py, pz), M[7]);
            float z = __fadd_rn(dotrow(M + 8, px, py, pz), M[11]);
            float zs = (fabsf(z) < 1e-6f) ? 1e-6f : z;
            int u = proj_pix(s_in[v*4+0], s_in[v*4+2], x, zs);
            int w = proj_pix(s_in[v*4+1], s_in[v*4+3], y, zs);
            if (!(z > 0.025f && z < 100.0f && u >= 0 && u < WSZ && w >= 0 && w < HSZ))
                continue;
            int pix = v * NPIX + w * WSZ + u;
            float df = __uint_as_float(~g_dflat[pix]);   // exact min-z (bit round-trip)
            if (z <= __fadd_rn(df, 1e-6f)) {
                float rx = dotrow(M,     na, nb, nc);
                float ry = dotrow(M + 4, na, nb, nc);
                float rz = dotrow(M + 8, na, nb, nc);
                float ss = __fadd_rn(__fadd_rn(__fmul_rn(rx, rx), __fmul_rn(ry, ry)),
                                     __fmul_rn(rz, rz));
                float len = fmaxf(__fsqrt_rn(ss), 1e-5f);
                float* base = &g_ns4[pix].x;
                atomicAdd(base + 0, __fdiv_rn(-rx, len));
                atomicAdd(base + 1, __fdiv_rn(-ry, len));
                atomicAdd(base + 2, __fdiv_rn(-rz, len));
                atomicAdd(base + 3, 1.f);
            }
        }
        return;
    }
    // ---- depth-image min/max (float4-vectorized) ----
    int b = blockIdx.x - projB;
    int v = b / PIXB4;
    int p4 = (b % PIXB4) * blockDim.x + threadIdx.x;
    uint4 raw = reinterpret_cast<const uint4*>(g_dflat)[v * (NPIX/4) + p4];
    float d0 = raw.x ? __fmul_rn(__uint_as_float(~raw.x), 0.04f) : 0.f;
    float d1 = raw.y ? __fmul_rn(__uint_as_float(~raw.y), 0.04f) : 0.f;
    float d2 = raw.z ? __fmul_rn(__uint_as_float(~raw.z), 0.04f) : 0.f;
    float d3 = raw.w ? __fmul_rn(__uint_as_float(~raw.w), 0.04f) : 0.f;
    float mnd = fminf(fminf(d0, d1), fminf(d2, d3));
    float mxd = fmaxf(fmaxf(d0, d1), fmaxf(d2, d3));
    for (int o = 16; o; o >>= 1) {
        mnd = fminf(mnd, __shfl_down_sync(0xffffffffu, mnd, o));
        mxd = fmaxf(mxd, __shfl_down_sync(0xffffffffu, mxd, o));
    }
    __shared__ float smnd[8], smxd[8];
    int wid = threadIdx.x >> 5, lid = threadIdx.x & 31;
    if (lid == 0) { smnd[wid] = mnd; smxd[wid] = mxd; }
    __syncthreads();
    if (threadIdx.x == 0) {
        for (int w = 1; w < 8; w++) { mnd = fminf(mnd, smnd[w]); mxd = fmaxf(mxd, smxd[w]); }
        atomicMax(&g_dminE[v], ~__float_as_uint(mnd));
        atomicMax(&g_dmax[v],   __float_as_uint(mxd));
    }
}

// --- L4: finalize images (1 px/thread, no self-clean stores) ----------------
__global__ void k_final(const float* __restrict__ tgt, float* __restrict__ out) {
    int v = blockIdx.y;
    int p = blockIdx.x * blockDim.x + threadIdx.x;
    int gp = v * NPIX + p;
    unsigned raw = g_dflat[gp];
    bool hit = raw != 0u;
    float dimg = hit ? __fmul_rn(__uint_as_float(~raw), 0.04f) : 0.f;
    float dmn = __uint_as_float(~g_dminE[v]);
    float sd  = __fsub_rn(dimg, dmn);
    float drg = __fsub_rn(__uint_as_float(g_dmax[v]), dmn);
    float dn = (drg != 0.f) ? __fdiv_rn(sd, drg) : sd;
    float dt = tgt[gp];
    float tmn = __uint_as_float(~g_tminE[v]);
    float st  = __fsub_rn(dt, tmn);
    float trg = __fsub_rn(__uint_as_float(g_tmax[v]), tmn);
    float tn = (trg != 0.f) ? __fdiv_rn(st, trg) : st;
    __stcs(&out[1 + gp], dn);                          // streaming: don't pollute L2
    __stcs(&out[1 + NVW * NPIX + gp], tn);
    if (hit) {                                         // !hit => ns4 provably zero
        float4 ns = g_ns4[gp];
        float cn = fmaxf(ns.w, 1.f);
        __stcs(&out[1 + 2 * NVW * NPIX + 3 * gp + 0], __fdiv_rn(ns.x, cn));
        __stcs(&out[1 + 2 * NVW * NPIX + 3 * gp + 1], __fdiv_rn(ns.y, cn));
        __stcs(&out[1 + 2 * NVW * NPIX + 3 * gp + 2], __fdiv_rn(ns.z, cn));
    } else {
        __stcs(&out[1 + 2 * NVW * NPIX + 3 * gp + 0], 0.f);
        __stcs(&out[1 + 2 * NVW * NPIX + 3 * gp + 1], 0.f);
        __stcs(&out[1 + 2 * NVW * NPIX + 3 * gp + 2], 0.f);
    }
    float l = (dt != 0.f) ? fabsf(__fsub_rn(dn, tn)) : 0.f;
    for (int o = 16; o; o >>= 1) l += __shfl_down_sync(0xffffffffu, l, o);
    __shared__ float sl[8];
    int wid = threadIdx.x >> 5, lid = threadIdx.x & 31;
    if (lid == 0) sl[wid] = l;
    __syncthreads();
    if (threadIdx.x == 0) {
        for (int w = 1; w < 8; w++) l += sl[w];
        atomicAdd(&g_lsum[v], l);
    }
}

// ---------------- L5: loss + scalar self-clean ------------------------------
__global__ void k_loss(float* __restrict__ out) {
    if (threadIdx.x == 0) {
        float tot = 0.f;
        for (int v = 0; v < NVW; v++) {
            float c = (float)g_vcnt[v];
            float l = (g_vcnt[v] > 0) ? __fdiv_rn(g_lsum[v], fmaxf(c, 1.f)) : 0.f;
            tot = __fadd_rn(tot, __fdiv_rn(l, 9.0f));   // * WEIGHT(1) / N_VIEWS
            g_lsum[v] = 0.f; g_vcnt[v] = 0;             // self-clean
            g_dminE[v] = 0u; g_tminE[v] = 0u;
            g_dmax[v] = 0u;  g_tmax[v] = 0u;
        }
        out[0] = tot;
    }
}

// ---------------------------------------------------------------------------
extern "C" void kernel_launch(void* const* d_in, const int* in_sizes, int n_in,
                              void* d_out, int out_size) {
    const int4*  coords = (const int4*) d_in[0];
    const float* origin = (const float*)d_in[1];
    const float* sdf    = (const float*)d_in[2];
    // d_in[3] = sdf_target (unused by forward)
    const float* tgt    = (const float*)d_in[4];
    const float* intr   = (const float*)d_in[5];
    const float* vm     = (const float*)d_in[6];
    float* out = (float*)d_out;

    int n = in_sizes[0] / 4;
    const int tb = 256;
    int projB = (n + tb - 1) / tb;

    k_scatter_tmm<<<projB + TMMB + DFZB, tb>>>(coords, tgt, n, projB);
    k_grid_project<<<projB + GRIDB + NSZB, tb>>>(coords, origin, vm, intr, sdf, n, projB);
    k_splat_dmm<<<projB + TMMB, tb>>>(coords, origin, vm, intr, n, projB);
    dim3 rg(PIXB, NVW);
    k_final<<<rg, tb>>>(tgt, out);
    k_loss<<<1, 32>>>(out);
}

// round 11
// speedup vs baseline: 1.3166x; 1.3166x over previous
#include <cuda_runtime.h>

#define NVW   9
#define HSZ   480
#define WSZ   640
#define NPIX  (HSZ*WSZ)
#define GD    96
#define NCELL (GD*GD*GD)
#define PIXB4 (NPIX/(256*4))   // 300 blocks per view image (4 px/thread)
#define PIXB  (NPIX/256)       // 1200 blocks per view image (1 px/thread)
#define GRIDB (NCELL/256)      // 3456 blocks for voxel grid
#define TMMB  (NVW*PIXB4)      // 2700 target-minmax blocks
#define DMMV  (NPIX/(256*2))   // 600 depth-minmax blocks per view (2 px/thread)

// ==== zero-canonical scratch: .bss zero == canonical empty; consumers   ====
// ==== restore what they consume (g_last by grid, g_dz by final, scalars ====
// ==== by loss; g_grid fully rewritten each call).                       ====
__device__ __align__(16) int                g_last[NCELL];   // idx+1, 0 = empty
__device__ float                            g_grid[NCELL];
// packed z-buffer: stores ~((zbits<<32)|idx); atomicMax == min over (z,idx); 0 = no hit
__device__ __align__(16) unsigned long long g_dz[NVW*NPIX];
__device__ unsigned int g_dminE[NVW], g_tminE[NVW];  // ~bits of min (atomicMax, 0-canonical)
__device__ unsigned int g_dmax[NVW],  g_tmax[NVW];   // bits of max (vals>=0, 0-canonical)
__device__ float        g_lsum[NVW];
__device__ int          g_vcnt[NVW];

// XLA:CPU dot (no FMA contraction, left-assoc, strict rn): ((p0*m0 + p1*m1) + p2*m2)
__device__ __forceinline__ float dotrow(const float* M, float px, float py, float pz) {
    return __fadd_rn(__fadd_rn(__fmul_rn(px, M[0]), __fmul_rn(py, M[1])),
                     __fmul_rn(pz, M[2]));
}
// u = rn( (f*x)/zs + c ), strict
__device__ __forceinline__ int proj_pix(float f, float c, float x, float zs) {
    return __float2int_rn(__fadd_rn(__fdiv_rn(__fmul_rn(f, x), zs), c));
}

__device__ __forceinline__ void load_view_consts(const float* __restrict__ vm,
                                                 const float* __restrict__ intr,
                                                 float* s_vm, float* s_in) {
    int t = threadIdx.x;
    if (t < NVW * 12) s_vm[t] = vm[(t / 12) * 16 + (t % 12)];   // rows 0..2 of 4x4
    if (t < NVW * 4) {
        int v = t >> 2, k = t & 3;
        int off = (k == 0) ? 0 : (k == 1) ? 5 : (k == 2) ? 2 : 6; // fx,fy,cx,cy
        s_in[t] = intr[v * 16 + off];
    }
    __syncthreads();
}

// ---- L1 fused: [0,projB) scatter ; [projB,..) target-image min/max/count --
__global__ void k_scatter_tmm(const int4* __restrict__ coords,
                              const float* __restrict__ tgt, int n, int projB) {
    if ((int)blockIdx.x < projB) {
        int i = blockIdx.x * blockDim.x + threadIdx.x;
        if (i >= n) return;
        int4 q = coords[i];                    // (.x=0, .y=c1, .z=c2, .w=c3)
        atomicMax(&g_last[(q.w * GD + q.z) * GD + q.y], i + 1);  // last-write-wins
        return;
    }
    int b = blockIdx.x - projB;
    int v = b / PIXB4;
    int p4 = (b % PIXB4) * blockDim.x + threadIdx.x;
    float4 dt = reinterpret_cast<const float4*>(tgt)[v * (NPIX/4) + p4];
    float mnt = fminf(fminf(dt.x, dt.y), fminf(dt.z, dt.w));
    float mxt = fmaxf(fmaxf(dt.x, dt.y), fmaxf(dt.z, dt.w));
    int cnt = (dt.x != 0.f) + (dt.y != 0.f) + (dt.z != 0.f) + (dt.w != 0.f);
    for (int o = 16; o; o >>= 1) {
        mnt = fminf(mnt, __shfl_down_sync(0xffffffffu, mnt, o));
        mxt = fmaxf(mxt, __shfl_down_sync(0xffffffffu, mxt, o));
        cnt += __shfl_down_sync(0xffffffffu, cnt, o);
    }
    __shared__ float smnt[8], smxt[8];
    __shared__ int sc[8];
    int wid = threadIdx.x >> 5, lid = threadIdx.x & 31;
    if (lid == 0) { smnt[wid] = mnt; smxt[wid] = mxt; sc[wid] = cnt; }
    __syncthreads();
    if (threadIdx.x == 0) {
        for (int w = 1; w < 8; w++) {
            mnt = fminf(mnt, smnt[w]); mxt = fmaxf(mxt, smxt[w]); cnt += sc[w];
        }
        atomicMax(&g_tminE[v], ~__float_as_uint(mnt));   // encoded min (0-canonical)
        atomicMax(&g_tmax[v],   __float_as_uint(mxt));
        atomicAdd(&g_vcnt[v], cnt);
    }
}

// -- L2 fused: [0,GRIDB) grid materialize+clean ; [GRIDB,..) project (u64) --
__global__ void k_grid_project(const int4* __restrict__ coords,
                               const float* __restrict__ origin,
                               const float* __restrict__ vm,
                               const float* __restrict__ intr,
                               const float* __restrict__ sdf, int n) {
    if (blockIdx.x < GRIDB) {
        int c = blockIdx.x * blockDim.x + threadIdx.x;
        int idx = g_last[c];
        g_grid[c] = (idx > 0) ? __ldg(&sdf[idx - 1]) : 0.f;
        if (idx > 0) g_last[c] = 0;                     // self-clean (skip if clean)
        return;
    }
    __shared__ float s_vm[NVW * 12];
    __shared__ float s_in[NVW * 4];
    load_view_consts(vm, intr, s_vm, s_in);
    int i = (blockIdx.x - GRIDB) * blockDim.x + threadIdx.x;
    if (i >= n) return;
    int4 q = coords[i];
    float px = __fadd_rn((float)q.w, __ldg(&origin[0]));
    float py = __fadd_rn((float)q.z, __ldg(&origin[1]));
    float pz = __fadd_rn((float)q.y, __ldg(&origin[2]));
    #pragma unroll
    for (int v = 0; v < NVW; v++) {
        const float* M = &s_vm[v * 12];
        float x = __fadd_rn(dotrow(M,     px, py, pz), M[3]);
        float y = __fadd_rn(dotrow(M + 4, px, py, pz), M[7]);
        float z = __fadd_rn(dotrow(M + 8, px, py, pz), M[11]);
        float zs = (fabsf(z) < 1e-6f) ? 1e-6f : z;
        int u = proj_pix(s_in[v*4+0], s_in[v*4+2], x, zs);
        int w = proj_pix(s_in[v*4+1], s_in[v*4+3], y, zs);
        if (z > 0.025f && z < 100.0f && u >= 0 && u < WSZ && w >= 0 && w < HSZ) {
            unsigned long long packed =
                ((unsigned long long)__float_as_uint(z) << 32) | (unsigned)i;
            atomicMax(&g_dz[v * NPIX + w * WSZ + u], ~packed);  // == min (z, idx)
        }
    }
}

// ------ L3: depth-image min/max over completed z-buffer (2 px/thread) ------
__global__ void k_dmm() {
    int v = blockIdx.x / DMMV;
    int p2 = (blockIdx.x % DMMV) * blockDim.x + threadIdx.x;
    ulonglong2 raw = reinterpret_cast<const ulonglong2*>(g_dz)[v * (NPIX/2) + p2];
    float d0 = raw.x ? __fmul_rn(__uint_as_float((unsigned)(~raw.x >> 32)), 0.04f) : 0.f;
    float d1 = raw.y ? __fmul_rn(__uint_as_float((unsigned)(~raw.y >> 32)), 0.04f) : 0.f;
    float mnd = fminf(d0, d1);
    float mxd = fmaxf(d0, d1);
    for (int o = 16; o; o >>= 1) {
        mnd = fminf(mnd, __shfl_down_sync(0xffffffffu, mnd, o));
        mxd = fmaxf(mxd, __shfl_down_sync(0xffffffffu, mxd, o));
    }
    __shared__ float smnd[8], smxd[8];
    int wid = threadIdx.x >> 5, lid = threadIdx.x & 31;
    if (lid == 0) { smnd[wid] = mnd; smxd[wid] = mxd; }
    __syncthreads();
    if (threadIdx.x == 0) {
        for (int w = 1; w < 8; w++) { mnd = fminf(mnd, smnd[w]); mxd = fmaxf(mxd, smxd[w]); }
        atomicMax(&g_dminE[v], ~__float_as_uint(mnd));
        atomicMax(&g_dmax[v],   __float_as_uint(mxd));
    }
}

// --- L4: finalize — depth/tgt normalize + per-pixel winner-normal + loss ---
__global__ void k_final(const int4* __restrict__ coords,
                        const float* __restrict__ vm,
                        const float* __restrict__ tgt, float* __restrict__ out) {
    int v = blockIdx.y;
    __shared__ float s_M[12];
    if (threadIdx.x < 12) s_M[threadIdx.x] = vm[v * 16 + threadIdx.x];  // rows 0..2
    __syncthreads();
    int p = blockIdx.x * blockDim.x + threadIdx.x;
    int gp = v * NPIX + p;
    unsigned long long raw = g_dz[gp];
    bool hit = raw != 0ull;
    unsigned long long packed = ~raw;
    float dimg = hit ? __fmul_rn(__uint_as_float((unsigned)(packed >> 32)), 0.04f) : 0.f;
    float dmn = __uint_as_float(~g_dminE[v]);
    float sd  = __fsub_rn(dimg, dmn);
    float drg = __fsub_rn(__uint_as_float(g_dmax[v]), dmn);
    float dn = (drg != 0.f) ? __fdiv_rn(sd, drg) : sd;
    float dt = tgt[gp];
    float tmn = __uint_as_float(~g_tminE[v]);
    float st  = __fsub_rn(dt, tmn);
    float trg = __fsub_rn(__uint_as_float(g_tmax[v]), tmn);
    float tn = (trg != 0.f) ? __fdiv_rn(st, trg) : st;
    __stcs(&out[1 + gp], dn);                          // streaming: don't pollute L2
    __stcs(&out[1 + NVW * NPIX + gp], tn);
    float* nout = &out[1 + 2 * NVW * NPIX + 3 * gp];
    if (hit) {
        int4 q = coords[(unsigned)(packed & 0xffffffffu)];   // winning point
        float na = 0.f, nb = 0.f, nc = 0.f;                   // central-diff normal
        if (q.w >= 1 && q.w <= GD-2 && q.z >= 1 && q.z <= GD-2 && q.y >= 1 && q.y <= GD-2) {
            int base = (q.w * GD + q.z) * GD + q.y;
            na = __fsub_rn(g_grid[base + 1],     g_grid[base - 1]);
            nb = __fsub_rn(g_grid[base + GD],    g_grid[base - GD]);
            nc = __fsub_rn(g_grid[base + GD*GD], g_grid[base - GD*GD]);
        }
        float rx = dotrow(s_M,     na, nb, nc);
        float ry = dotrow(s_M + 4, na, nb, nc);
        float rz = dotrow(s_M + 8, na, nb, nc);
        float ss = __fadd_rn(__fadd_rn(__fmul_rn(rx, rx), __fmul_rn(ry, ry)),
                             __fmul_rn(rz, rz));
        float len = fmaxf(__fsqrt_rn(ss), 1e-5f);
        __stcs(nout + 0, __fdiv_rn(-rx, len));
        __stcs(nout + 1, __fdiv_rn(-ry, len));
        __stcs(nout + 2, __fdiv_rn(-rz, len));
        g_dz[gp] = 0ull;                               // self-clean
    } else {
        __stcs(nout + 0, 0.f);
        __stcs(nout + 1, 0.f);
        __stcs(nout + 2, 0.f);
    }
    float l = (dt != 0.f) ? fabsf(__fsub_rn(dn, tn)) : 0.f;
    for (int o = 16; o; o >>= 1) l += __shfl_down_sync(0xffffffffu, l, o);
    __shared__ float sl[8];
    int wid = threadIdx.x >> 5, lid = threadIdx.x & 31;
    if (lid == 0) sl[wid] = l;
    __syncthreads();
    if (threadIdx.x == 0) {
        for (int w = 1; w < 8; w++) l += sl[w];
        atomicAdd(&g_lsum[v], l);
    }
}

// ---------------- L5: loss + scalar self-clean ------------------------------
__global__ void k_loss(float* __restrict__ out) {
    if (threadIdx.x == 0) {
        float tot = 0.f;
        for (int v = 0; v < NVW; v++) {
            float c = (float)g_vcnt[v];
            float l = (g_vcnt[v] > 0) ? __fdiv_rn(g_lsum[v], fmaxf(c, 1.f)) : 0.f;
            tot = __fadd_rn(tot, __fdiv_rn(l, 9.0f));   // * WEIGHT(1) / N_VIEWS
            g_lsum[v] = 0.f; g_vcnt[v] = 0;             // self-clean
            g_dminE[v] = 0u; g_tminE[v] = 0u;
            g_dmax[v] = 0u;  g_tmax[v] = 0u;
        }
        out[0] = tot;
    }
}

// ---------------------------------------------------------------------------
extern "C" void kernel_launch(void* const* d_in, const int* in_sizes, int n_in,
                              void* d_out, int out_size) {
    const int4*  coords = (const int4*) d_in[0];
    const float* origin = (const float*)d_in[1];
    const float* sdf    = (const float*)d_in[2];
    // d_in[3] = sdf_target (unused by forward)
    const float* tgt    = (const float*)d_in[4];
    const float* intr   = (const float*)d_in[5];
    const float* vm     = (const float*)d_in[6];
    float* out = (float*)d_out;

    int n = in_sizes[0] / 4;
    const int tb = 256;
    int projB = (n + tb - 1) / tb;

    k_scatter_tmm<<<projB + TMMB, tb>>>(coords, tgt, n, projB);
    k_grid_project<<<GRIDB + projB, tb>>>(coords, origin, vm, intr, sdf, n);
    k_dmm<<<NVW * DMMV, tb>>>();
    dim3 rg(PIXB, NVW);
    k_final<<<rg, tb>>>(coords, vm, tgt, out);
    k_loss<<<1, 32>>>(out);
}